// round 1
// baseline (speedup 1.0000x reference)
#include <cuda_runtime.h>
#include <cuda_bf16.h>
#include <cstdint>

// Problem constants
#define T_STEPS 256
#define BSZ     25
#define VOCAB   32000
#define HID     1024
#define NCLS    2
#define MROWS   (T_STEPS * BSZ)   // 6400

#define NBLK_RECUR 128

// ---------------- scratch (device globals; no runtime allocation) ----------------
__device__ float g_Z[MROWS * HID];          // 26.2 MB: X @ W_xh for all timesteps
__device__ float g_WhhT[HID * HID];         // 4 MB: W_hh transposed [col][k]
__device__ float g_h[2][BSZ * HID];         // ping-pong hidden state
__device__ int g_bar_cnt;
__device__ volatile unsigned g_bar_gen;

// ---------------- helpers ----------------
__device__ __forceinline__ float f2tf(float x) {
    uint32_t u;
    asm("cvt.rna.tf32.f32 %0, %1;" : "=r"(u) : "f"(x));
    return __uint_as_float(u);
}

__device__ __forceinline__ void mma_tf32(float* c, const float* a, const float* b) {
    asm volatile(
        "mma.sync.aligned.m16n8k8.row.col.f32.tf32.tf32.f32 "
        "{%0,%1,%2,%3}, {%4,%5,%6,%7}, {%8,%9}, {%0,%1,%2,%3};\n"
        : "+f"(c[0]), "+f"(c[1]), "+f"(c[2]), "+f"(c[3])
        : "r"(__float_as_uint(a[0])), "r"(__float_as_uint(a[1])),
          "r"(__float_as_uint(a[2])), "r"(__float_as_uint(a[3])),
          "r"(__float_as_uint(b[0])), "r"(__float_as_uint(b[1])));
}

// ---------------- init: zero h0, reset barrier ----------------
__global__ void init_k() {
    int tid = blockIdx.x * 256 + threadIdx.x;
    if (tid == 0) { g_bar_cnt = 0; g_bar_gen = 0u; }
    if (tid < BSZ * HID) g_h[0][tid] = 0.0f;
}

// ---------------- W_hh transpose: g_WhhT[c][k] = W_hh[k][c] ----------------
__global__ void transpose_k(const float* __restrict__ W) {
    __shared__ float tile[32][33];
    int x = blockIdx.x * 32 + threadIdx.x;
    int y = blockIdx.y * 32 + threadIdx.y;
    #pragma unroll
    for (int i = 0; i < 32; i += 8)
        tile[threadIdx.y + i][threadIdx.x] = W[(y + i) * HID + x];
    __syncthreads();
    x = blockIdx.y * 32 + threadIdx.x;
    y = blockIdx.x * 32 + threadIdx.y;
    #pragma unroll
    for (int i = 0; i < 32; i += 8)
        g_WhhT[(y + i) * HID + x] = tile[threadIdx.x][threadIdx.y + i];
}

// ---------------- Phase 1: Z = X @ W_xh  (TF32 mma.sync) ----------------
// A: [6400][32000] row-major, B: [32000][1024] row-major, C=g_Z: [6400][1024]
// CTA tile 128x128, BK=16. 256 threads = 8 warps in 4(m) x 2(n) grid;
// warp tile 32x64 => 2 m16 tiles x 8 n8 tiles.
__global__ void __launch_bounds__(256) gemm_tf32(const float* __restrict__ A,
                                                 const float* __restrict__ B) {
    __shared__ float As[16][136];   // [k][m], pad 8 -> conflict-free frag loads
    __shared__ float Bs[16][136];   // [k][n], pad 8

    const int tid  = threadIdx.x;
    const int lane = tid & 31;
    const int warp = tid >> 5;
    const int wm   = warp & 3;   // m offset wm*32
    const int wn   = warp >> 2;  // n offset wn*64
    const int m0   = blockIdx.y * 128;
    const int n0   = blockIdx.x * 128;

    float acc[2][8][4];
    #pragma unroll
    for (int mi = 0; mi < 2; mi++)
        #pragma unroll
        for (int ni = 0; ni < 8; ni++)
            #pragma unroll
            for (int j = 0; j < 4; j++) acc[mi][ni][j] = 0.0f;

    const int ar  = tid >> 1;         // 0..127 (A row within tile)
    const int akb = (tid & 1) * 8;    // k offset 0/8
    const float* aptr = A + (size_t)(m0 + ar) * VOCAB + akb;

    const int bkr = tid >> 5;         // 0..7 (B row within tile, second at +8)
    const int bc4 = lane << 2;        // col within tile (float4)
    const float* bptr = B + (size_t)bkr * HID + n0 + bc4;

    for (int k0 = 0; k0 < VOCAB; k0 += 16) {
        float4 av0 = *(const float4*)(aptr);
        float4 av1 = *(const float4*)(aptr + 4);
        float4 bv0 = *(const float4*)(bptr);
        float4 bv1 = *(const float4*)(bptr + 8 * HID);

        As[akb + 0][ar] = f2tf(av0.x);
        As[akb + 1][ar] = f2tf(av0.y);
        As[akb + 2][ar] = f2tf(av0.z);
        As[akb + 3][ar] = f2tf(av0.w);
        As[akb + 4][ar] = f2tf(av1.x);
        As[akb + 5][ar] = f2tf(av1.y);
        As[akb + 6][ar] = f2tf(av1.z);
        As[akb + 7][ar] = f2tf(av1.w);

        Bs[bkr][bc4 + 0]     = f2tf(bv0.x);
        Bs[bkr][bc4 + 1]     = f2tf(bv0.y);
        Bs[bkr][bc4 + 2]     = f2tf(bv0.z);
        Bs[bkr][bc4 + 3]     = f2tf(bv0.w);
        Bs[bkr + 8][bc4 + 0] = f2tf(bv1.x);
        Bs[bkr + 8][bc4 + 1] = f2tf(bv1.y);
        Bs[bkr + 8][bc4 + 2] = f2tf(bv1.z);
        Bs[bkr + 8][bc4 + 3] = f2tf(bv1.w);

        __syncthreads();

        #pragma unroll
        for (int kk = 0; kk < 16; kk += 8) {
            float af[2][4];
            float bf[8][2];
            const int ak = kk + (lane & 3);
            const int rg = lane >> 2;  // group id 0..7
            #pragma unroll
            for (int mi = 0; mi < 2; mi++) {
                const int mb = wm * 32 + mi * 16;
                af[mi][0] = As[ak][mb + rg];
                af[mi][1] = As[ak][mb + 8 + rg];
                af[mi][2] = As[ak + 4][mb + rg];
                af[mi][3] = As[ak + 4][mb + 8 + rg];
            }
            #pragma unroll
            for (int ni = 0; ni < 8; ni++) {
                const int nb = wn * 64 + ni * 8 + rg;
                bf[ni][0] = Bs[ak][nb];
                bf[ni][1] = Bs[ak + 4][nb];
            }
            #pragma unroll
            for (int mi = 0; mi < 2; mi++)
                #pragma unroll
                for (int ni = 0; ni < 8; ni++)
                    mma_tf32(acc[mi][ni], af[mi], bf[ni]);
        }

        __syncthreads();
        aptr += 16;
        bptr += (size_t)16 * HID;
    }

    // store C
    const int rg = lane >> 2;
    const int cg = (lane & 3) * 2;
    #pragma unroll
    for (int mi = 0; mi < 2; mi++) {
        #pragma unroll
        for (int ni = 0; ni < 8; ni++) {
            int row = m0 + wm * 32 + mi * 16 + rg;
            int col = n0 + wn * 64 + ni * 8 + cg;
            g_Z[(size_t)row * HID + col]           = acc[mi][ni][0];
            g_Z[(size_t)row * HID + col + 1]       = acc[mi][ni][1];
            g_Z[(size_t)(row + 8) * HID + col]     = acc[mi][ni][2];
            g_Z[(size_t)(row + 8) * HID + col + 1] = acc[mi][ni][3];
        }
    }
}

// ---------------- grid barrier (all 128 CTAs resident) ----------------
__device__ __forceinline__ void grid_sync() {
    __syncthreads();
    if (threadIdx.x == 0) {
        __threadfence();
        unsigned gen = g_bar_gen;
        if (atomicAdd(&g_bar_cnt, 1) == NBLK_RECUR - 1) {
            g_bar_cnt = 0;
            __threadfence();
            g_bar_gen = gen + 1u;
        } else {
            while (g_bar_gen == gen) { }
        }
    }
    __syncthreads();
}

// ---------------- Phase 2: persistent recurrence over 256 steps ----------------
// 128 CTAs x 256 threads. Each warp owns one output column (8 cols/CTA),
// lanes stride K; h chunk staged in smem; 25 row-accumulators in registers.
__global__ void __launch_bounds__(256) rnn_recur(const float* __restrict__ b_h) {
    __shared__ float sh[BSZ][128];
    const int tid  = threadIdx.x;
    const int lane = tid & 31;
    const int warp = tid >> 5;
    const int col  = blockIdx.x * 8 + warp;
    const float* wrow = g_WhhT + (size_t)col * HID;
    const float bias = b_h[col];

    for (int t = 0; t < T_STEPS; t++) {
        const float* hin  = g_h[t & 1];
        float*       hout = g_h[(t + 1) & 1];
        const float* Zt   = g_Z + (size_t)t * BSZ * HID;

        float acc[BSZ];
        #pragma unroll
        for (int r = 0; r < BSZ; r++) acc[r] = 0.0f;

        for (int kc = 0; kc < HID; kc += 128) {
            __syncthreads();
            #pragma unroll
            for (int i = 0; i < 13; i++) {
                int idx = tid + i * 256;
                if (idx < BSZ * 128)
                    sh[idx >> 7][idx & 127] = hin[((idx >> 7) << 10) + kc + (idx & 127)];
            }
            __syncthreads();
            #pragma unroll
            for (int i = 0; i < 4; i++) {
                float w = wrow[kc + i * 32 + lane];
                #pragma unroll
                for (int r = 0; r < BSZ; r++)
                    acc[r] += sh[r][i * 32 + lane] * w;
            }
        }

        #pragma unroll
        for (int r = 0; r < BSZ; r++) {
            float v = acc[r];
            #pragma unroll
            for (int off = 16; off; off >>= 1)
                v += __shfl_xor_sync(0xffffffffu, v, off);
            if (lane == 0)
                hout[(r << 10) + col] = tanhf(Zt[(r << 10) + col] + v + bias);
        }

        grid_sync();
    }
}

// ---------------- Phase 3: pool + FC + softmax ----------------
__global__ void final_k(const float* __restrict__ fc_w,
                        const float* __restrict__ fc_b,
                        float* __restrict__ out) {
    __shared__ float s0[256], s1[256];
    const float* h = g_h[0];  // after 256 steps, result is in buffer 0
    int tid = threadIdx.x;
    float l0 = 0.0f, l1 = 0.0f;
    for (int j = tid; j < HID; j += 256) {
        float p = 0.0f;
        #pragma unroll
        for (int r = 0; r < BSZ; r++) p += h[r * HID + j];
        p *= (1.0f / (float)BSZ);
        l0 += p * fc_w[j * NCLS + 0];
        l1 += p * fc_w[j * NCLS + 1];
    }
    s0[tid] = l0; s1[tid] = l1;
    __syncthreads();
    for (int s = 128; s; s >>= 1) {
        if (tid < s) { s0[tid] += s0[tid + s]; s1[tid] += s1[tid + s]; }
        __syncthreads();
    }
    if (tid == 0) {
        float a = s0[0] + fc_b[0];
        float b = s1[0] + fc_b[1];
        float m = fmaxf(a, b);
        float e0 = expf(a - m), e1 = expf(b - m);
        float inv = 1.0f / (e0 + e1);
        out[0] = e0 * inv;
        out[1] = e1 * inv;
    }
}

// ---------------- launch ----------------
extern "C" void kernel_launch(void* const* d_in, const int* in_sizes, int n_in,
                              void* d_out, int out_size) {
    const float* X   = (const float*)d_in[0];
    const float* Wxh = (const float*)d_in[1];
    const float* Whh = (const float*)d_in[2];
    const float* bh  = (const float*)d_in[3];
    const float* fcw = (const float*)d_in[4];
    const float* fcb = (const float*)d_in[5];
    float* out = (float*)d_out;

    init_k<<<100, 256>>>();
    transpose_k<<<dim3(32, 32), dim3(32, 8)>>>(Whh);
    gemm_tf32<<<dim3(8, 50), 256>>>(X, Wxh);
    rnn_recur<<<NBLK_RECUR, 256>>>(bh);
    final_k<<<1, 256>>>(fcw, fcb, out);
}

// round 5
// speedup vs baseline: 1.7397x; 1.7397x over previous
#include <cuda_runtime.h>
#include <cuda_bf16.h>
#include <cstdint>

// Problem constants
#define T_STEPS 256
#define BSZ     25
#define VOCAB   32000
#define HID     1024
#define NCLS    2
#define MROWS   (T_STEPS * BSZ)   // 6400

#define NBLK_RECUR 128

// ---------------- scratch (device globals; no runtime allocation) ----------------
__device__ float g_Z[MROWS * HID];          // 26.2 MB: X @ W_xh for all timesteps
__device__ float g_WhhT[HID * HID];         // 4 MB: W_hh transposed [col][k]
__device__ float g_h[2][BSZ * HID];         // ping-pong hidden state
__device__ int g_bar_cnt;
__device__ volatile unsigned g_bar_gen;

// ---------------- helpers ----------------
__device__ __forceinline__ void mma_tf32(float* c, const float* a, const float* b) {
    asm volatile(
        "mma.sync.aligned.m16n8k8.row.col.f32.tf32.tf32.f32 "
        "{%0,%1,%2,%3}, {%4,%5,%6,%7}, {%8,%9}, {%0,%1,%2,%3};\n"
        : "+f"(c[0]), "+f"(c[1]), "+f"(c[2]), "+f"(c[3])
        : "r"(__float_as_uint(a[0])), "r"(__float_as_uint(a[1])),
          "r"(__float_as_uint(a[2])), "r"(__float_as_uint(a[3])),
          "r"(__float_as_uint(b[0])), "r"(__float_as_uint(b[1])));
}

__device__ __forceinline__ void cpa16(uint32_t dst, const void* src) {
    asm volatile("cp.async.cg.shared.global [%0], [%1], 16;\n"
                 :: "r"(dst), "l"(src));
}
__device__ __forceinline__ void cpa_commit() {
    asm volatile("cp.async.commit_group;\n" ::: "memory");
}
template <int N>
__device__ __forceinline__ void cpa_wait() {
    asm volatile("cp.async.wait_group %0;\n" :: "n"(N) : "memory");
}

// ---------------- init: zero h0, reset barrier ----------------
__global__ void init_k() {
    int tid = blockIdx.x * 256 + threadIdx.x;
    if (tid == 0) { g_bar_cnt = 0; g_bar_gen = 0u; }
    if (tid < BSZ * HID) g_h[0][tid] = 0.0f;
}

// ---------------- W_hh transpose: g_WhhT[c][k] = W_hh[k][c] ----------------
__global__ void transpose_k(const float* __restrict__ W) {
    __shared__ float tile[32][33];
    int x = blockIdx.x * 32 + threadIdx.x;
    int y = blockIdx.y * 32 + threadIdx.y;
    #pragma unroll
    for (int i = 0; i < 32; i += 8)
        tile[threadIdx.y + i][threadIdx.x] = W[(y + i) * HID + x];
    __syncthreads();
    x = blockIdx.y * 32 + threadIdx.x;
    y = blockIdx.x * 32 + threadIdx.y;
    #pragma unroll
    for (int i = 0; i < 32; i += 8)
        g_WhhT[(y + i) * HID + x] = tile[threadIdx.x][threadIdx.y + i];
}

// ---------------- Phase 1: Z = X @ W_xh  (TF32 mma.sync, cp.async 2-stage) ----------------
// A: [6400][32000] row-major, B: [32000][1024] row-major, C=g_Z: [6400][1024]
// CTA tile 128x128, BK=16, double-buffered cp.async. 256 threads = 8 warps,
// 4(m) x 2(n); warp tile 32x64 => 2 m16 tiles x 8 n8 tiles.
// As[stage][m][k] pad 4 (row stride 20 floats); Bs[stage][k][n] pad 8 (136).
__global__ void __launch_bounds__(256) gemm_tf32(const float* __restrict__ A,
                                                 const float* __restrict__ B) {
    __shared__ float As[2][128][20];
    __shared__ float Bs[2][16][136];

    const int tid  = threadIdx.x;
    const int lane = tid & 31;
    const int warp = tid >> 5;
    const int wm   = warp & 3;   // m offset wm*32
    const int wn   = warp >> 2;  // n offset wn*64
    const int m0   = blockIdx.y * 128;
    const int n0   = blockIdx.x * 128;

    float acc[2][8][4];
    #pragma unroll
    for (int mi = 0; mi < 2; mi++)
        #pragma unroll
        for (int ni = 0; ni < 8; ni++)
            #pragma unroll
            for (int j = 0; j < 4; j++) acc[mi][ni][j] = 0.0f;

    // cp.async source/dest mapping
    // A: 128 rows x 4 chunks (16B) per row = 512 chunks; thread does chunk tid, tid+256
    const int arow = tid >> 2;          // 0..63
    const int akq  = (tid & 3) * 4;     // 0,4,8,12
    const float* ag0 = A + (size_t)(m0 + arow) * VOCAB + akq;
    const float* ag1 = ag0 + (size_t)64 * VOCAB;
    // B: 16 rows x 32 chunks per row = 512 chunks; thread does chunk tid, tid+256
    const int brow = tid >> 5;          // 0..7
    const int bnq  = (tid & 31) * 4;
    const float* bg0 = B + (size_t)brow * HID + n0 + bnq;
    const float* bg1 = bg0 + (size_t)8 * HID;

    const uint32_t as_base = (uint32_t)__cvta_generic_to_shared(&As[0][0][0]);
    const uint32_t bs_base = (uint32_t)__cvta_generic_to_shared(&Bs[0][0][0]);
    const uint32_t asd = as_base + arow * 80 + akq * 4;   // row stride 20 floats
    const uint32_t bsd = bs_base + brow * 544 + bnq * 4;  // row stride 136 floats
    const uint32_t AS_STG = 128 * 20 * 4;   // 10240
    const uint32_t BS_STG = 16 * 136 * 4;   // 8704

    const int NIT = VOCAB / 16;  // 2000

    // prefetch stage 0
    cpa16(asd, ag0);
    cpa16(asd + 64 * 80, ag1);
    cpa16(bsd, bg0);
    cpa16(bsd + 8 * 544, bg1);
    cpa_commit();

    const int rg = lane >> 2;
    const int l3 = lane & 3;

    #pragma unroll 1
    for (int it = 0; it < NIT; it++) {
        const int cur = it & 1;
        if (it + 1 < NIT) {
            const int nxt = cur ^ 1;
            const size_t ko  = (size_t)(it + 1) * 16;
            cpa16(asd + nxt * AS_STG, ag0 + ko);
            cpa16(asd + 64 * 80 + nxt * AS_STG, ag1 + ko);
            cpa16(bsd + nxt * BS_STG, bg0 + ko * HID);
            cpa16(bsd + 8 * 544 + nxt * BS_STG, bg1 + ko * HID);
            cpa_commit();
            cpa_wait<1>();
        } else {
            cpa_wait<0>();
        }
        __syncthreads();

        #pragma unroll
        for (int kk = 0; kk < 16; kk += 8) {
            const int ak = kk + l3;
            float af[2][4];
            float bf[8][2];
            #pragma unroll
            for (int mi = 0; mi < 2; mi++) {
                const int mb = wm * 32 + mi * 16;
                af[mi][0] = As[cur][mb + rg][ak];
                af[mi][1] = As[cur][mb + 8 + rg][ak];
                af[mi][2] = As[cur][mb + rg][ak + 4];
                af[mi][3] = As[cur][mb + 8 + rg][ak + 4];
            }
            #pragma unroll
            for (int ni = 0; ni < 8; ni++) {
                const int nb = wn * 64 + ni * 8 + rg;
                bf[ni][0] = Bs[cur][ak][nb];
                bf[ni][1] = Bs[cur][ak + 4][nb];
            }
            #pragma unroll
            for (int mi = 0; mi < 2; mi++)
                #pragma unroll
                for (int ni = 0; ni < 8; ni++)
                    mma_tf32(acc[mi][ni], af[mi], bf[ni]);
        }

        __syncthreads();
    }

    // store C
    const int cg = (lane & 3) * 2;
    #pragma unroll
    for (int mi = 0; mi < 2; mi++) {
        #pragma unroll
        for (int ni = 0; ni < 8; ni++) {
            int row = m0 + wm * 32 + mi * 16 + rg;
            int col = n0 + wn * 64 + ni * 8 + cg;
            g_Z[(size_t)row * HID + col]           = acc[mi][ni][0];
            g_Z[(size_t)row * HID + col + 1]       = acc[mi][ni][1];
            g_Z[(size_t)(row + 8) * HID + col]     = acc[mi][ni][2];
            g_Z[(size_t)(row + 8) * HID + col + 1] = acc[mi][ni][3];
        }
    }
}

// ---------------- grid barrier (all 128 CTAs resident) ----------------
__device__ __forceinline__ void grid_sync() {
    __syncthreads();
    if (threadIdx.x == 0) {
        __threadfence();
        unsigned gen = g_bar_gen;
        if (atomicAdd(&g_bar_cnt, 1) == NBLK_RECUR - 1) {
            g_bar_cnt = 0;
            __threadfence();
            g_bar_gen = gen + 1u;
        } else {
            while (g_bar_gen == gen) { }
        }
    }
    __syncthreads();
}

// ---------------- Phase 2: persistent recurrence over 256 steps ----------------
// 128 CTAs x 256 threads; CTA owns 8 output columns. Thread = (row r, col c):
// r = tid>>3 (rows 0..31, only r<25 active), c = tid&7. Each active thread
// computes the complete 1024-length dot h_in[r] . WhhT[col] -> no shuffles.
// h chunk staged in smem with 8-lane broadcast reads; W slice (32KB) staged
// once in smem for all 256 steps. Packed fma.rn.f32x2 for the dot.
__global__ void __launch_bounds__(256) rnn_recur(const float* __restrict__ b_h) {
    __shared__ float w_s[8][1028];   // pad 4 -> conflict-free 8-col reads
    __shared__ float sh[BSZ][132];   // pad 4 -> conflict-free 4-row reads

    const int tid = threadIdx.x;
    const int r   = tid >> 3;   // 0..31
    const int c   = tid & 7;
    const int col = blockIdx.x * 8 + c;

    // stage W slice once: 8 cols x 1024 floats = 2048 float4, 8 per thread
    #pragma unroll
    for (int j = tid; j < 2048; j += 256) {
        int cc = j >> 8;             // 0..7
        int kq = (j & 255) * 4;
        *(float4*)&w_s[cc][kq] =
            *(const float4*)&g_WhhT[(size_t)(blockIdx.x * 8 + cc) * HID + kq];
    }
    const float bias = b_h[col];

    const uint32_t sh_b = (uint32_t)__cvta_generic_to_shared(&sh[0][0]);
    const uint32_t ws_b = (uint32_t)__cvta_generic_to_shared(&w_s[0][0]);
    const uint32_t sh_r = sh_b + r * 528;       // row stride 132 floats
    const uint32_t ws_c = ws_b + c * 4112;      // col stride 1028 floats

    __syncthreads();

    for (int t = 0; t < T_STEPS; t++) {
        const float* hin  = g_h[t & 1];
        float*       hout = g_h[(t + 1) & 1];
        const float* Zt   = g_Z + (size_t)t * BSZ * HID;

        unsigned long long a0 = 0ull, a1 = 0ull;  // packed f32x2 accumulators

        for (int kc = 0; kc < HID; kc += 128) {
            __syncthreads();
            // stage h chunk: 25 rows x 32 float4 = 800 float4
            #pragma unroll
            for (int j = tid; j < 800; j += 256) {
                int rr = j >> 5;
                int kq = (j & 31) * 4;
                *(float4*)&sh[rr][kq] = *(const float4*)&hin[rr * HID + kc + kq];
            }
            __syncthreads();

            if (r < BSZ) {
                #pragma unroll
                for (int i = 0; i < 32; i++) {
                    unsigned long long h01, h23, v01, v23;
                    asm("ld.shared.v2.u64 {%0,%1}, [%2];"
                        : "=l"(h01), "=l"(h23) : "r"(sh_r + i * 16));
                    asm("ld.shared.v2.u64 {%0,%1}, [%2];"
                        : "=l"(v01), "=l"(v23) : "r"(ws_c + (kc + i * 4) * 4));
                    asm("fma.rn.f32x2 %0, %1, %2, %0;" : "+l"(a0) : "l"(h01), "l"(v01));
                    asm("fma.rn.f32x2 %0, %1, %2, %0;" : "+l"(a1) : "l"(h23), "l"(v23));
                }
            }
        }

        if (r < BSZ) {
            float x0, x1, y0, y1;
            asm("mov.b64 {%0,%1}, %2;" : "=f"(x0), "=f"(x1) : "l"(a0));
            asm("mov.b64 {%0,%1}, %2;" : "=f"(y0), "=f"(y1) : "l"(a1));
            float v = (x0 + x1) + (y0 + y1);
            hout[r * HID + col] = tanhf(Zt[r * HID + col] + v + bias);
        }

        grid_sync();
    }
}

// ---------------- Phase 3: pool + FC + softmax ----------------
__global__ void final_k(const float* __restrict__ fc_w,
                        const float* __restrict__ fc_b,
                        float* __restrict__ out) {
    __shared__ float s0[256], s1[256];
    const float* h = g_h[0];  // after 256 steps, result is in buffer 0
    int tid = threadIdx.x;
    float l0 = 0.0f, l1 = 0.0f;
    for (int j = tid; j < HID; j += 256) {
        float p = 0.0f;
        #pragma unroll
        for (int r = 0; r < BSZ; r++) p += h[r * HID + j];
        p *= (1.0f / (float)BSZ);
        l0 += p * fc_w[j * NCLS + 0];
        l1 += p * fc_w[j * NCLS + 1];
    }
    s0[tid] = l0; s1[tid] = l1;
    __syncthreads();
    for (int s = 128; s; s >>= 1) {
        if (tid < s) { s0[tid] += s0[tid + s]; s1[tid] += s1[tid + s]; }
        __syncthreads();
    }
    if (tid == 0) {
        float a = s0[0] + fc_b[0];
        float b = s1[0] + fc_b[1];
        float m = fmaxf(a, b);
        float e0 = expf(a - m), e1 = expf(b - m);
        float inv = 1.0f / (e0 + e1);
        out[0] = e0 * inv;
        out[1] = e1 * inv;
    }
}

// ---------------- launch ----------------
extern "C" void kernel_launch(void* const* d_in, const int* in_sizes, int n_in,
                              void* d_out, int out_size) {
    const float* X   = (const float*)d_in[0];
    const float* Wxh = (const float*)d_in[1];
    const float* Whh = (const float*)d_in[2];
    const float* bh  = (const float*)d_in[3];
    const float* fcw = (const float*)d_in[4];
    const float* fcb = (const float*)d_in[5];
    float* out = (float*)d_out;

    init_k<<<100, 256>>>();
    transpose_k<<<dim3(32, 32), dim3(32, 8)>>>(Whh);
    gemm_tf32<<<dim3(8, 50), 256>>>(X, Wxh);
    rnn_recur<<<NBLK_RECUR, 256>>>(bh);
    final_k<<<1, 256>>>(fcw, fcb, out);
}

// round 6
// speedup vs baseline: 1.7495x; 1.0056x over previous
#include <cuda_runtime.h>
#include <cuda_bf16.h>
#include <cstdint>

// Problem constants
#define T_STEPS 256
#define BSZ     25
#define VOCAB   32000
#define HID     1024
#define NCLS    2
#define MROWS   (T_STEPS * BSZ)   // 6400

#define NBLK_RECUR 128

// ---------------- scratch (device globals; no runtime allocation) ----------------
__device__ float g_Z[MROWS * HID];          // 26.2 MB: X @ W_xh for all timesteps
__device__ float g_WhhT[HID * HID];         // 4 MB: W_hh transposed [col][k]
__device__ float g_h[2][BSZ * HID];         // ping-pong hidden state
__device__ int g_bar_cnt;
__device__ volatile unsigned g_bar_gen;

// ---------------- helpers ----------------
__device__ __forceinline__ void mma_tf32(float* c, const float* a, const float* b) {
    asm volatile(
        "mma.sync.aligned.m16n8k8.row.col.f32.tf32.tf32.f32 "
        "{%0,%1,%2,%3}, {%4,%5,%6,%7}, {%8,%9}, {%0,%1,%2,%3};\n"
        : "+f"(c[0]), "+f"(c[1]), "+f"(c[2]), "+f"(c[3])
        : "r"(__float_as_uint(a[0])), "r"(__float_as_uint(a[1])),
          "r"(__float_as_uint(a[2])), "r"(__float_as_uint(a[3])),
          "r"(__float_as_uint(b[0])), "r"(__float_as_uint(b[1])));
}

__device__ __forceinline__ void cpa16(uint32_t dst, const void* src) {
    asm volatile("cp.async.cg.shared.global [%0], [%1], 16;\n"
                 :: "r"(dst), "l"(src));
}
__device__ __forceinline__ void cpa_commit() {
    asm volatile("cp.async.commit_group;\n" ::: "memory");
}
template <int N>
__device__ __forceinline__ void cpa_wait() {
    asm volatile("cp.async.wait_group %0;\n" :: "n"(N) : "memory");
}

// ---------------- init: zero h0, reset barrier ----------------
__global__ void init_k() {
    int tid = blockIdx.x * 256 + threadIdx.x;
    if (tid == 0) { g_bar_cnt = 0; g_bar_gen = 0u; }
    if (tid < BSZ * HID) g_h[0][tid] = 0.0f;
}

// ---------------- W_hh transpose: g_WhhT[c][k] = W_hh[k][c] ----------------
__global__ void transpose_k(const float* __restrict__ W) {
    __shared__ float tile[32][33];
    int x = blockIdx.x * 32 + threadIdx.x;
    int y = blockIdx.y * 32 + threadIdx.y;
    #pragma unroll
    for (int i = 0; i < 32; i += 8)
        tile[threadIdx.y + i][threadIdx.x] = W[(y + i) * HID + x];
    __syncthreads();
    x = blockIdx.y * 32 + threadIdx.x;
    y = blockIdx.x * 32 + threadIdx.y;
    #pragma unroll
    for (int i = 0; i < 32; i += 8)
        g_WhhT[(y + i) * HID + x] = tile[threadIdx.x][threadIdx.y + i];
}

// ---------------- Phase 1: Z = X @ W_xh  (TF32 mma.sync, cp.async 2-stage) ----------------
// A: [6400][32000] row-major, B: [32000][1024] row-major, C=g_Z: [6400][1024]
// CTA tile 128x128, BK=16, double-buffered cp.async. 256 threads = 8 warps,
// 4(m) x 2(n); warp tile 32x64 => 2 m16 tiles x 8 n8 tiles.
// As[stage][m][k] pad 4 (row stride 20 floats); Bs[stage][k][n] pad 8 (136).
__global__ void __launch_bounds__(256) gemm_tf32(const float* __restrict__ A,
                                                 const float* __restrict__ B) {
    __shared__ float As[2][128][20];
    __shared__ float Bs[2][16][136];

    const int tid  = threadIdx.x;
    const int lane = tid & 31;
    const int warp = tid >> 5;
    const int wm   = warp & 3;   // m offset wm*32
    const int wn   = warp >> 2;  // n offset wn*64
    const int m0   = blockIdx.y * 128;
    const int n0   = blockIdx.x * 128;

    float acc[2][8][4];
    #pragma unroll
    for (int mi = 0; mi < 2; mi++)
        #pragma unroll
        for (int ni = 0; ni < 8; ni++)
            #pragma unroll
            for (int j = 0; j < 4; j++) acc[mi][ni][j] = 0.0f;

    // cp.async source/dest mapping
    // A: 128 rows x 4 chunks (16B) per row = 512 chunks; thread does chunk tid, tid+256
    const int arow = tid >> 2;          // 0..63
    const int akq  = (tid & 3) * 4;     // 0,4,8,12
    const float* ag0 = A + (size_t)(m0 + arow) * VOCAB + akq;
    const float* ag1 = ag0 + (size_t)64 * VOCAB;
    // B: 16 rows x 32 chunks per row = 512 chunks; thread does chunk tid, tid+256
    const int brow = tid >> 5;          // 0..7
    const int bnq  = (tid & 31) * 4;
    const float* bg0 = B + (size_t)brow * HID + n0 + bnq;
    const float* bg1 = bg0 + (size_t)8 * HID;

    const uint32_t as_base = (uint32_t)__cvta_generic_to_shared(&As[0][0][0]);
    const uint32_t bs_base = (uint32_t)__cvta_generic_to_shared(&Bs[0][0][0]);
    const uint32_t asd = as_base + arow * 80 + akq * 4;   // row stride 20 floats
    const uint32_t bsd = bs_base + brow * 544 + bnq * 4;  // row stride 136 floats
    const uint32_t AS_STG = 128 * 20 * 4;   // 10240
    const uint32_t BS_STG = 16 * 136 * 4;   // 8704

    const int NIT = VOCAB / 16;  // 2000

    // prefetch stage 0
    cpa16(asd, ag0);
    cpa16(asd + 64 * 80, ag1);
    cpa16(bsd, bg0);
    cpa16(bsd + 8 * 544, bg1);
    cpa_commit();

    const int rg = lane >> 2;
    const int l3 = lane & 3;

    #pragma unroll 1
    for (int it = 0; it < NIT; it++) {
        const int cur = it & 1;
        if (it + 1 < NIT) {
            const int nxt = cur ^ 1;
            const size_t ko  = (size_t)(it + 1) * 16;
            cpa16(asd + nxt * AS_STG, ag0 + ko);
            cpa16(asd + 64 * 80 + nxt * AS_STG, ag1 + ko);
            cpa16(bsd + nxt * BS_STG, bg0 + ko * HID);
            cpa16(bsd + 8 * 544 + nxt * BS_STG, bg1 + ko * HID);
            cpa_commit();
            cpa_wait<1>();
        } else {
            cpa_wait<0>();
        }
        __syncthreads();

        #pragma unroll
        for (int kk = 0; kk < 16; kk += 8) {
            const int ak = kk + l3;
            float af[2][4];
            float bf[8][2];
            #pragma unroll
            for (int mi = 0; mi < 2; mi++) {
                const int mb = wm * 32 + mi * 16;
                af[mi][0] = As[cur][mb + rg][ak];
                af[mi][1] = As[cur][mb + 8 + rg][ak];
                af[mi][2] = As[cur][mb + rg][ak + 4];
                af[mi][3] = As[cur][mb + 8 + rg][ak + 4];
            }
            #pragma unroll
            for (int ni = 0; ni < 8; ni++) {
                const int nb = wn * 64 + ni * 8 + rg;
                bf[ni][0] = Bs[cur][ak][nb];
                bf[ni][1] = Bs[cur][ak + 4][nb];
            }
            #pragma unroll
            for (int mi = 0; mi < 2; mi++)
                #pragma unroll
                for (int ni = 0; ni < 8; ni++)
                    mma_tf32(acc[mi][ni], af[mi], bf[ni]);
        }

        __syncthreads();
    }

    // store C
    const int cg = (lane & 3) * 2;
    #pragma unroll
    for (int mi = 0; mi < 2; mi++) {
        #pragma unroll
        for (int ni = 0; ni < 8; ni++) {
            int row = m0 + wm * 32 + mi * 16 + rg;
            int col = n0 + wn * 64 + ni * 8 + cg;
            g_Z[(size_t)row * HID + col]           = acc[mi][ni][0];
            g_Z[(size_t)row * HID + col + 1]       = acc[mi][ni][1];
            g_Z[(size_t)(row + 8) * HID + col]     = acc[mi][ni][2];
            g_Z[(size_t)(row + 8) * HID + col + 1] = acc[mi][ni][3];
        }
    }
}

// ---------------- grid barrier (all 128 CTAs resident) ----------------
__device__ __forceinline__ void grid_sync() {
    __syncthreads();
    if (threadIdx.x == 0) {
        __threadfence();
        unsigned gen = g_bar_gen;
        if (atomicAdd(&g_bar_cnt, 1) == NBLK_RECUR - 1) {
            g_bar_cnt = 0;
            __threadfence();
            g_bar_gen = gen + 1u;
        } else {
            while (g_bar_gen == gen) { }
        }
    }
    __syncthreads();
}

// ---------------- Phase 2: persistent recurrence over 256 steps ----------------
// 128 CTAs x 256 threads; CTA owns 8 output columns. Thread = (row r, col c):
// r = tid>>3 (rows 0..31, only r<25 active), c = tid&7. Each active thread
// computes the complete 1024-length dot h_in[r] . WhhT[col] -> no shuffles.
// h chunk staged in smem with 8-lane broadcast reads; W slice (32KB) staged
// once in smem for all 256 steps. Packed fma.rn.f32x2 for the dot.
__global__ void __launch_bounds__(256) rnn_recur(const float* __restrict__ b_h) {
    __shared__ float w_s[8][1028];   // pad 4 -> conflict-free 8-col reads
    __shared__ float sh[BSZ][132];   // pad 4 -> conflict-free 4-row reads

    const int tid = threadIdx.x;
    const int r   = tid >> 3;   // 0..31
    const int c   = tid & 7;
    const int col = blockIdx.x * 8 + c;

    // stage W slice once: 8 cols x 1024 floats = 2048 float4, 8 per thread
    #pragma unroll
    for (int j = tid; j < 2048; j += 256) {
        int cc = j >> 8;             // 0..7
        int kq = (j & 255) * 4;
        *(float4*)&w_s[cc][kq] =
            *(const float4*)&g_WhhT[(size_t)(blockIdx.x * 8 + cc) * HID + kq];
    }
    const float bias = b_h[col];

    const uint32_t sh_b = (uint32_t)__cvta_generic_to_shared(&sh[0][0]);
    const uint32_t ws_b = (uint32_t)__cvta_generic_to_shared(&w_s[0][0]);
    const uint32_t sh_r = sh_b + r * 528;       // row stride 132 floats
    const uint32_t ws_c = ws_b + c * 4112;      // col stride 1028 floats

    __syncthreads();

    for (int t = 0; t < T_STEPS; t++) {
        const float* hin  = g_h[t & 1];
        float*       hout = g_h[(t + 1) & 1];
        const float* Zt   = g_Z + (size_t)t * BSZ * HID;

        unsigned long long a0 = 0ull, a1 = 0ull;  // packed f32x2 accumulators

        for (int kc = 0; kc < HID; kc += 128) {
            __syncthreads();
            // stage h chunk: 25 rows x 32 float4 = 800 float4
            #pragma unroll
            for (int j = tid; j < 800; j += 256) {
                int rr = j >> 5;
                int kq = (j & 31) * 4;
                *(float4*)&sh[rr][kq] = *(const float4*)&hin[rr * HID + kc + kq];
            }
            __syncthreads();

            if (r < BSZ) {
                #pragma unroll
                for (int i = 0; i < 32; i++) {
                    unsigned long long h01, h23, v01, v23;
                    asm("ld.shared.v2.u64 {%0,%1}, [%2];"
                        : "=l"(h01), "=l"(h23) : "r"(sh_r + i * 16));
                    asm("ld.shared.v2.u64 {%0,%1}, [%2];"
                        : "=l"(v01), "=l"(v23) : "r"(ws_c + (kc + i * 4) * 4));
                    asm("fma.rn.f32x2 %0, %1, %2, %0;" : "+l"(a0) : "l"(h01), "l"(v01));
                    asm("fma.rn.f32x2 %0, %1, %2, %0;" : "+l"(a1) : "l"(h23), "l"(v23));
                }
            }
        }

        if (r < BSZ) {
            float x0, x1, y0, y1;
            asm("mov.b64 {%0,%1}, %2;" : "=f"(x0), "=f"(x1) : "l"(a0));
            asm("mov.b64 {%0,%1}, %2;" : "=f"(y0), "=f"(y1) : "l"(a1));
            float v = (x0 + x1) + (y0 + y1);
            hout[r * HID + col] = tanhf(Zt[r * HID + col] + v + bias);
        }

        grid_sync();
    }
}

// ---------------- Phase 3: pool + FC + softmax ----------------
__global__ void final_k(const float* __restrict__ fc_w,
                        const float* __restrict__ fc_b,
                        float* __restrict__ out) {
    __shared__ float s0[256], s1[256];
    const float* h = g_h[0];  // after 256 steps, result is in buffer 0
    int tid = threadIdx.x;
    float l0 = 0.0f, l1 = 0.0f;
    for (int j = tid; j < HID; j += 256) {
        float p = 0.0f;
        #pragma unroll
        for (int r = 0; r < BSZ; r++) p += h[r * HID + j];
        p *= (1.0f / (float)BSZ);
        l0 += p * fc_w[j * NCLS + 0];
        l1 += p * fc_w[j * NCLS + 1];
    }
    s0[tid] = l0; s1[tid] = l1;
    __syncthreads();
    for (int s = 128; s; s >>= 1) {
        if (tid < s) { s0[tid] += s0[tid + s]; s1[tid] += s1[tid + s]; }
        __syncthreads();
    }
    if (tid == 0) {
        float a = s0[0] + fc_b[0];
        float b = s1[0] + fc_b[1];
        float m = fmaxf(a, b);
        float e0 = expf(a - m), e1 = expf(b - m);
        float inv = 1.0f / (e0 + e1);
        out[0] = e0 * inv;
        out[1] = e1 * inv;
    }
}

// ---------------- launch ----------------
extern "C" void kernel_launch(void* const* d_in, const int* in_sizes, int n_in,
                              void* d_out, int out_size) {
    const float* X   = (const float*)d_in[0];
    const float* Wxh = (const float*)d_in[1];
    const float* Whh = (const float*)d_in[2];
    const float* bh  = (const float*)d_in[3];
    const float* fcw = (const float*)d_in[4];
    const float* fcb = (const float*)d_in[5];
    float* out = (float*)d_out;

    init_k<<<100, 256>>>();
    transpose_k<<<dim3(32, 32), dim3(32, 8)>>>(Whh);
    gemm_tf32<<<dim3(8, 50), 256>>>(X, Wxh);
    rnn_recur<<<NBLK_RECUR, 256>>>(bh);
    final_k<<<1, 256>>>(fcw, fcb, out);
}

// round 8
// speedup vs baseline: 2.1657x; 1.2379x over previous
#include <cuda_runtime.h>
#include <cuda_fp16.h>
#include <cstdint>

#define T_STEPS 256
#define BSZ     25
#define VOCAB   32000
#define HID     1024
#define NCLS    2
#define MROWS   6400
#define NBLK_RECUR 128
#define KT      1000           // k-tiles of 32 (32000/32)
#define TILEB   8192           // bytes per packed tile (128 rows x 32 k x fp16)

// ---------------- device scratch ----------------
__device__ float g_Z[MROWS * HID];                        // 26 MB
__device__ float g_WhhT[HID * HID];                       // 4 MB
__device__ float g_h[2][BSZ * HID];
__device__ __align__(256) uint8_t g_Apk[(size_t)50 * KT * TILEB];  // 409.6 MB
__device__ __align__(256) uint8_t g_Bpk[(size_t)8  * KT * TILEB];  // 65.5 MB
__device__ int   g_flags[NBLK_RECUR * 32];
__device__ volatile int g_rel;

// ---------------- helpers ----------------
__device__ __forceinline__ uint32_t s2u(const void* p) {
    uint32_t a;
    asm("{ .reg .u64 t; cvta.to.shared.u64 t, %1; cvt.u32.u64 %0, t; }" : "=r"(a) : "l"(p));
    return a;
}
__device__ __forceinline__ void mbar_init(uint32_t m, uint32_t c) {
    asm volatile("mbarrier.init.shared.b64 [%0], %1;" :: "r"(m), "r"(c) : "memory");
}
__device__ __forceinline__ void mbar_expect(uint32_t m, uint32_t bytes) {
    asm volatile("mbarrier.arrive.expect_tx.shared.b64 _, [%0], %1;" :: "r"(m), "r"(bytes) : "memory");
}
__device__ __forceinline__ void mbar_wait(uint32_t m, uint32_t ph) {
    asm volatile(
        "{\n\t.reg .pred P;\n\t"
        "W%=:\n\t"
        "mbarrier.try_wait.parity.acquire.cta.shared::cta.b64 P, [%0], %1, 0x989680;\n\t"
        "@P bra.uni D%=;\n\t"
        "bra.uni W%=;\n\t"
        "D%=:\n\t}" :: "r"(m), "r"(ph) : "memory");
}
__device__ __forceinline__ void bulk_g2s(uint32_t dst, const void* src, uint32_t bytes, uint32_t mbar) {
    asm volatile(
        "cp.async.bulk.shared::cluster.global.mbarrier::complete_tx::bytes [%0], [%1], %2, [%3];"
        :: "r"(dst), "l"(src), "r"(bytes), "r"(mbar) : "memory");
}
__device__ __forceinline__ void hmma(float* c, uint32_t a0, uint32_t a1, uint32_t a2,
                                     uint32_t a3, uint32_t b0, uint32_t b1) {
    asm volatile(
        "mma.sync.aligned.m16n8k16.row.col.f32.f16.f16.f32 "
        "{%0,%1,%2,%3}, {%4,%5,%6,%7}, {%8,%9}, {%0,%1,%2,%3};\n"
        : "+f"(c[0]), "+f"(c[1]), "+f"(c[2]), "+f"(c[3])
        : "r"(a0), "r"(a1), "r"(a2), "r"(a3), "r"(b0), "r"(b1));
}

// packed in-row byte offset for original k within a 32-k row (fragment-ordered)
// pair p=k>>1: stored slot q = (p&3)*4 + (p>>2); byte = q*4 + (k&1)*2
__device__ __forceinline__ uint32_t koff_pair(int p) {  // byte offset of pair p
    return (uint32_t)((p & 3) * 16 + (p >> 2) * 4);
}

// ---------------- init ----------------
__global__ void init_k() {
    int tid = blockIdx.x * 256 + threadIdx.x;
    if (tid == 0) g_rel = 0;
    if (tid < NBLK_RECUR * 32) g_flags[tid] = 0;
    if (tid < BSZ * HID) g_h[0][tid] = 0.0f;
}

// ---------------- W_hh transpose ----------------
__global__ void transpose_k(const float* __restrict__ W) {
    __shared__ float tile[32][33];
    int x = blockIdx.x * 32 + threadIdx.x;
    int y = blockIdx.y * 32 + threadIdx.y;
    #pragma unroll
    for (int i = 0; i < 32; i += 8)
        tile[threadIdx.y + i][threadIdx.x] = W[(y + i) * HID + x];
    __syncthreads();
    x = blockIdx.y * 32 + threadIdx.x;
    y = blockIdx.x * 32 + threadIdx.y;
    #pragma unroll
    for (int i = 0; i < 32; i += 8)
        g_WhhT[(y + i) * HID + x] = tile[threadIdx.x][threadIdx.y + i];
}

// ---------------- packA: X -> fp16 fragment-ordered tiles ----------------
// tile (kt=bx, mb=by): 128 m-rows x 32 k, 64B/row. 2048 pairs, 8 per thread.
__global__ void __launch_bounds__(256) packA(const float* __restrict__ X) {
    const int kt = blockIdx.x, mb = blockIdx.y;
    uint8_t* dst = g_Apk + ((size_t)mb * KT + kt) * TILEB;
    const float* src = X + (size_t)(mb * 128) * VOCAB + kt * 32;
    #pragma unroll
    for (int i = 0; i < 8; i++) {
        int idx = threadIdx.x + i * 256;
        int m = idx >> 4, p = idx & 15;
        float2 v = *(const float2*)&src[(size_t)m * VOCAB + p * 2];
        __half2 h = __floats2half2_rn(v.x, v.y);
        *(uint32_t*)(dst + m * 64 + koff_pair(p)) = *(uint32_t*)&h;
    }
}

// ---------------- packB: W_xh^T -> fp16 fragment-ordered tiles ----------------
// tile (kt=bx, nb=by): 128 n-rows x 32 k (transposed from W_xh [k][n])
__global__ void __launch_bounds__(256) packB(const float* __restrict__ Wxh) {
    __shared__ float s[32][132];
    const int kt = blockIdx.x, nb = blockIdx.y;
    uint8_t* dst = g_Bpk + ((size_t)nb * KT + kt) * TILEB;
    #pragma unroll
    for (int i = 0; i < 16; i++) {
        int idx = threadIdx.x + i * 256;
        int kk = idx >> 7, n = idx & 127;
        s[kk][n] = Wxh[(size_t)(kt * 32 + kk) * HID + nb * 128 + n];
    }
    __syncthreads();
    #pragma unroll
    for (int i = 0; i < 8; i++) {
        int idx = threadIdx.x + i * 256;
        int n = idx >> 4, p = idx & 15;
        __half2 h = __floats2half2_rn(s[2 * p][n], s[2 * p + 1][n]);
        *(uint32_t*)(dst + n * 64 + koff_pair(p)) = *(uint32_t*)&h;
    }
}

// ---------------- Phase 1: Z = X @ W_xh  (fp16 mma.sync + cp.async.bulk) ----------------
// grid (8 nb, 50 mb), 256 threads = 8 warps (4m x 2n), warp tile 32x64.
// BK=32, 2-stage bulk pipeline: per stage 1 bulk A (8KB) + 1 bulk B (8KB).
__global__ void __launch_bounds__(256) gemm_fp16() {
    __shared__ __align__(128) uint8_t sA[2][TILEB];
    __shared__ __align__(128) uint8_t sB[2][TILEB];
    __shared__ __align__(8) uint64_t s_full[2];

    const int tid  = threadIdx.x;
    const int lane = tid & 31;
    const int warp = tid >> 5;
    const int wm   = warp & 3;
    const int wn   = warp >> 2;
    const int g    = lane >> 2;   // group row/col
    const int tg   = lane & 3;
    const int nb   = blockIdx.x, mb = blockIdx.y;

    const uint32_t mb_full[2] = { s2u(&s_full[0]), s2u(&s_full[1]) };
    if (tid == 0) { mbar_init(mb_full[0], 1); mbar_init(mb_full[1], 1); }
    __syncthreads();

    const uint8_t* Ab = g_Apk + (size_t)mb * KT * TILEB;
    const uint8_t* Bb = g_Bpk + (size_t)nb * KT * TILEB;
    const uint32_t sa0 = s2u(&sA[0][0]), sb0 = s2u(&sB[0][0]);

    if (tid == 0) {
        #pragma unroll
        for (int s = 0; s < 2; s++) {
            mbar_expect(mb_full[s], 2 * TILEB);
            bulk_g2s(sa0 + s * TILEB, Ab + (size_t)s * TILEB, TILEB, mb_full[s]);
            bulk_g2s(sb0 + s * TILEB, Bb + (size_t)s * TILEB, TILEB, mb_full[s]);
        }
    }

    float acc[2][8][4];
    #pragma unroll
    for (int mi = 0; mi < 2; mi++)
        #pragma unroll
        for (int ni = 0; ni < 8; ni++)
            #pragma unroll
            for (int j = 0; j < 4; j++) acc[mi][ni][j] = 0.0f;

    // per-thread fragment addresses (within a stage)
    const uint32_t a_off = (uint32_t)((wm * 32 + g) * 64 + tg * 16);
    const uint32_t b_off = (uint32_t)((wn * 64 + g) * 64 + tg * 16);

    #pragma unroll 1
    for (int kt = 0; kt < KT; kt++) {
        const int s = kt & 1;
        const int ph = (kt >> 1) & 1;
        mbar_wait(mb_full[s], ph);

        const uint8_t* As = sA[s];
        const uint8_t* Bs = sB[s];

        // A fragments: one v4 per (mi, lo/hi-row)
        uint4 aL0 = *(const uint4*)(As + a_off);
        uint4 aH0 = *(const uint4*)(As + a_off + 512);
        uint4 aL1 = *(const uint4*)(As + a_off + 1024);
        uint4 aH1 = *(const uint4*)(As + a_off + 1536);

        #pragma unroll
        for (int ni = 0; ni < 8; ni++) {
            uint4 bf = *(const uint4*)(Bs + b_off + ni * 512);
            // kk = 0
            hmma(acc[0][ni], aL0.x, aH0.x, aL0.y, aH0.y, bf.x, bf.y);
            hmma(acc[1][ni], aL1.x, aH1.x, aL1.y, aH1.y, bf.x, bf.y);
            // kk = 16
            hmma(acc[0][ni], aL0.z, aH0.z, aL0.w, aH0.w, bf.z, bf.w);
            hmma(acc[1][ni], aL1.z, aH1.z, aL1.w, aH1.w, bf.z, bf.w);
        }

        __syncthreads();
        const int nk = kt + 2;
        if (tid == 0 && nk < KT) {
            mbar_expect(mb_full[s], 2 * TILEB);
            bulk_g2s(sa0 + s * TILEB, Ab + (size_t)nk * TILEB, TILEB, mb_full[s]);
            bulk_g2s(sb0 + s * TILEB, Bb + (size_t)nk * TILEB, TILEB, mb_full[s]);
        }
    }

    // store C
    const int cg = tg * 2;
    #pragma unroll
    for (int mi = 0; mi < 2; mi++) {
        #pragma unroll
        for (int ni = 0; ni < 8; ni++) {
            int row = mb * 128 + wm * 32 + mi * 16 + g;
            int col = nb * 128 + wn * 64 + ni * 8 + cg;
            g_Z[(size_t)row * HID + col]           = acc[mi][ni][0];
            g_Z[(size_t)row * HID + col + 1]       = acc[mi][ni][1];
            g_Z[(size_t)(row + 8) * HID + col]     = acc[mi][ni][2];
            g_Z[(size_t)(row + 8) * HID + col + 1] = acc[mi][ni][3];
        }
    }
}

// ---------------- distributed grid barrier ----------------
__device__ __forceinline__ void grid_sync2(int t) {
    __syncthreads();
    const int tid = threadIdx.x;
    if (tid == 0) {
        __threadfence();
        *(volatile int*)&g_flags[blockIdx.x * 32] = t + 1;
    }
    if (blockIdx.x == 0) {
        if (tid < NBLK_RECUR)
            while (*(volatile int*)&g_flags[tid * 32] <= t) { }
        __syncthreads();
        if (tid == 0) { __threadfence(); g_rel = t + 1; }
    }
    if (tid == 0) { while (g_rel <= t) { } }
    __syncthreads();
}

// ---------------- Phase 2: persistent recurrence ----------------
__global__ void __launch_bounds__(256) rnn_recur(const float* __restrict__ b_h) {
    __shared__ float w_s[8][1028];
    __shared__ float sh[BSZ][132];

    const int tid = threadIdx.x;
    const int r   = tid >> 3;
    const int c   = tid & 7;
    const int col = blockIdx.x * 8 + c;

    #pragma unroll
    for (int j = tid; j < 2048; j += 256) {
        int cc = j >> 8, kq = (j & 255) * 4;
        *(float4*)&w_s[cc][kq] =
            *(const float4*)&g_WhhT[(size_t)(blockIdx.x * 8 + cc) * HID + kq];
    }
    const float bias = b_h[col];
    const uint32_t sh_r = s2u(&sh[0][0]) + r * 528;
    const uint32_t ws_c = s2u(&w_s[0][0]) + c * 4112;
    __syncthreads();

    for (int t = 0; t < T_STEPS; t++) {
        const float* hin  = g_h[t & 1];
        float*       hout = g_h[(t + 1) & 1];
        const float* Zt   = g_Z + (size_t)t * BSZ * HID;

        unsigned long long a0 = 0ull, a1 = 0ull;
        for (int kc = 0; kc < HID; kc += 128) {
            __syncthreads();
            #pragma unroll
            for (int j = tid; j < 800; j += 256) {
                int rr = j >> 5, kq = (j & 31) * 4;
                *(float4*)&sh[rr][kq] = *(const float4*)&hin[rr * HID + kc + kq];
            }
            __syncthreads();
            if (r < BSZ) {
                #pragma unroll
                for (int i = 0; i < 32; i++) {
                    unsigned long long h01, h23, v01, v23;
                    asm("ld.shared.v2.u64 {%0,%1}, [%2];" : "=l"(h01), "=l"(h23) : "r"(sh_r + i * 16));
                    asm("ld.shared.v2.u64 {%0,%1}, [%2];" : "=l"(v01), "=l"(v23) : "r"(ws_c + (kc + i * 4) * 4));
                    asm("fma.rn.f32x2 %0, %1, %2, %0;" : "+l"(a0) : "l"(h01), "l"(v01));
                    asm("fma.rn.f32x2 %0, %1, %2, %0;" : "+l"(a1) : "l"(h23), "l"(v23));
                }
            }
        }
        if (r < BSZ) {
            float x0, x1, y0, y1;
            asm("mov.b64 {%0,%1}, %2;" : "=f"(x0), "=f"(x1) : "l"(a0));
            asm("mov.b64 {%0,%1}, %2;" : "=f"(y0), "=f"(y1) : "l"(a1));
            float v = (x0 + x1) + (y0 + y1);
            hout[r * HID + col] = tanhf(Zt[r * HID + col] + v + bias);
        }
        grid_sync2(t);
    }
}

// ---------------- Phase 3: pool + FC + softmax ----------------
__global__ void final_k(const float* __restrict__ fc_w,
                        const float* __restrict__ fc_b,
                        float* __restrict__ out) {
    __shared__ float s0[256], s1[256];
    const float* h = g_h[0];
    int tid = threadIdx.x;
    float l0 = 0.0f, l1 = 0.0f;
    for (int j = tid; j < HID; j += 256) {
        float p = 0.0f;
        #pragma unroll
        for (int rr = 0; rr < BSZ; rr++) p += h[rr * HID + j];
        p *= (1.0f / (float)BSZ);
        l0 += p * fc_w[j * NCLS + 0];
        l1 += p * fc_w[j * NCLS + 1];
    }
    s0[tid] = l0; s1[tid] = l1;
    __syncthreads();
    for (int s = 128; s; s >>= 1) {
        if (tid < s) { s0[tid] += s0[tid + s]; s1[tid] += s1[tid + s]; }
        __syncthreads();
    }
    if (tid == 0) {
        float a = s0[0] + fc_b[0];
        float b = s1[0] + fc_b[1];
        float m = fmaxf(a, b);
        float e0 = expf(a - m), e1 = expf(b - m);
        float inv = 1.0f / (e0 + e1);
        out[0] = e0 * inv;
        out[1] = e1 * inv;
    }
}

// ---------------- launch ----------------
extern "C" void kernel_launch(void* const* d_in, const int* in_sizes, int n_in,
                              void* d_out, int out_size) {
    const float* X   = (const float*)d_in[0];
    const float* Wxh = (const float*)d_in[1];
    const float* Whh = (const float*)d_in[2];
    const float* bh  = (const float*)d_in[3];
    const float* fcw = (const float*)d_in[4];
    const float* fcb = (const float*)d_in[5];
    float* out = (float*)d_out;

    init_k<<<100, 256>>>();
    transpose_k<<<dim3(32, 32), dim3(32, 8)>>>(Whh);
    packA<<<dim3(KT, 50), 256>>>(X);
    packB<<<dim3(KT, 8), 256>>>(Wxh);
    gemm_fp16<<<dim3(8, 50), 256>>>();
    rnn_recur<<<NBLK_RECUR, 256>>>(bh);
    final_k<<<1, 256>>>(fcw, fcb, out);
}